// round 4
// baseline (speedup 1.0000x reference)
#include <cuda_runtime.h>
#include <cuda_fp16.h>
#include <stdint.h>

// Problem dims (fixed by the dataset)
#define HID   4096
#define ISZ   11008
#define MROWS 4096   // 2 * 2048

// Scratch (allocation-free rule: __device__ globals). fp16 intermediates.
__device__ __half g_gate[(size_t)MROWS * ISZ];
__device__ __half g_up  [(size_t)MROWS * ISZ];

#define BM 128
#define BN 128
#define BK 64   // == GROUPSIZE/2 -> scale/zero constant within a K-tile

// Swizzled 32-bit LDS from a [rows][64 half] tile.
// Layout: 16B chunk c of row r stored at physical chunk (c ^ (r&7)).
__device__ __forceinline__ uint32_t lds_sw(const uint32_t* base, int r, int u) {
    int c = u >> 2;
    return base[r * 32 + (((c ^ (r & 7)) << 2) | (u & 3))];
}

__device__ __forceinline__ int4 pack8(float4 a, float4 b) {
    __align__(16) __half2 h[4];
    h[0] = __floats2half2_rn(a.x, a.y);
    h[1] = __floats2half2_rn(a.z, a.w);
    h[2] = __floats2half2_rn(b.x, b.y);
    h[3] = __floats2half2_rn(b.z, b.w);
    return *(const int4*)h;
}

// C[M,N] = A[M,K] @ dequant_gptq(qw, scales, zeros)[K,N]
// qw: [K/8, N] int32 (8 nibbles along K), scales: [K/128, N] fp32 (upcast fp16),
// zeros: [K/128, N/8] int32 (8 nibbles along N).  w[k,n] = (q - (z+1)) * s
// Grid: (N/BN, M/BM), 256 threads (8 warps as 2x4 -> warp tile 64x32).
// AT: float (input x) or __half (scratch). CT: __half (scratch) or float (out).
template <typename AT, typename CT>
__global__ __launch_bounds__(256, 2)
void gemm_gptq(const AT* __restrict__ A, const int* __restrict__ qw,
               const float* __restrict__ scales, const int* __restrict__ zeros,
               CT* __restrict__ C, int N, int K)
{
    __shared__ __align__(16) __half As[BM * BK];
    __shared__ __align__(16) __half Bs[BN * BK];   // [n][k] (k contiguous)

    const int t    = threadIdx.x;
    const int lane = t & 31;
    const int wid  = t >> 5;
    const int warp_m = wid >> 2;     // 0..1
    const int warp_n = wid & 3;      // 0..3
    const int bm = blockIdx.y * BM;
    const int bn = blockIdx.x * BN;

    // ---- A copy mapping: chunk id = t + i*256 -> row = t>>3 + i*32, chunk = t&7
    const int a_r0 = t >> 3;
    const int a_c  = t & 7;
    const AT* Aptr = A + (size_t)(bm + a_r0) * K + a_c * 8;

    // ---- B dequant mapping: word id = t + i*256 -> n = t&127, j = (t>>7) + 2i
    const int nb = t & 127;
    const int jb = t >> 7;
    const int* qptr = qw + (size_t)jb * N + bn + nb;
    const float* sptr = scales + bn + nb;
    const int*   zptr = zeros + ((bn + nb) >> 3);
    const int    zsh  = (nb & 7) * 4;

    float acc[4][4][4];
#pragma unroll
    for (int f = 0; f < 4; ++f)
#pragma unroll
        for (int n = 0; n < 4; ++n)
#pragma unroll
            for (int i = 0; i < 4; ++i) acc[f][n][i] = 0.f;

    const int ntiles = K / BK;
    int4   aR[4];      // used when AT == __half
    float4 aRf[8];     // used when AT == float
    int    bR[4];
    float  sF, zsF;

    // prefetch tile 0
    {
#pragma unroll
        for (int i = 0; i < 4; ++i) {
            if constexpr (sizeof(AT) == 2) {
                aR[i] = *(const int4*)(Aptr + (size_t)i * 32 * K);
            } else {
                aRf[2 * i]     = *(const float4*)(Aptr + (size_t)i * 32 * K);
                aRf[2 * i + 1] = *(const float4*)(Aptr + (size_t)i * 32 * K + 4);
            }
        }
#pragma unroll
        for (int i = 0; i < 4; ++i)
            bR[i] = qptr[(size_t)(2 * i) * N];
        sF = sptr[0];
        int zw = zptr[0];
        zsF = (float)(((zw >> zsh) & 15) + 1) * sF;
    }

    const uint32_t* As32 = (const uint32_t*)As;
    const uint32_t* Bs32 = (const uint32_t*)Bs;

    for (int kt = 0; kt < ntiles; ++kt) {
        __syncthreads();   // previous tile's compute finished reading smem

        // store A tile (swizzled 16B chunks, fp16)
#pragma unroll
        for (int i = 0; i < 4; ++i) {
            int r = a_r0 + i * 32;
            int4 v;
            if constexpr (sizeof(AT) == 2) v = aR[i];
            else                           v = pack8(aRf[2 * i], aRf[2 * i + 1]);
            ((int4*)As)[r * 8 + (a_c ^ (r & 7))] = v;
        }
        // dequant + store B tile
#pragma unroll
        for (int i = 0; i < 4; ++i) {
            int j = jb + 2 * i;
            uint32_t q = (uint32_t)bR[i];
            __align__(16) __half2 h[4];
#pragma unroll
            for (int p = 0; p < 4; ++p) {
                float f0 = fmaf((float)(q & 15u), sF, -zsF); q >>= 4;
                float f1 = fmaf((float)(q & 15u), sF, -zsF); q >>= 4;
                h[p] = __floats2half2_rn(f0, f1);
            }
            ((int4*)Bs)[nb * 8 + (j ^ (nb & 7))] = *(const int4*)h;
        }
        __syncthreads();   // tile ready

        // register-prefetch next tile (overlaps with MMA below)
        if (kt + 1 < ntiles) {
            int k0n = (kt + 1) * BK;
#pragma unroll
            for (int i = 0; i < 4; ++i) {
                if constexpr (sizeof(AT) == 2) {
                    aR[i] = *(const int4*)(Aptr + (size_t)i * 32 * K + k0n);
                } else {
                    aRf[2 * i]     = *(const float4*)(Aptr + (size_t)i * 32 * K + k0n);
                    aRf[2 * i + 1] = *(const float4*)(Aptr + (size_t)i * 32 * K + k0n + 4);
                }
            }
#pragma unroll
            for (int i = 0; i < 4; ++i)
                bR[i] = qptr[(size_t)((kt + 1) * 8 + 2 * i) * N];
            int g = (kt + 1) >> 1;   // BK=64 -> group flips every 2 tiles
            sF = sptr[(size_t)g * N];
            int zw = zptr[(size_t)g * (N >> 3)];
            zsF = (float)(((zw >> zsh) & 15) + 1) * sF;
        }

        // compute: 4 k-steps of 16
#pragma unroll
        for (int ks = 0; ks < 4; ++ks) {
            int ulo = ks * 8 + (lane & 3);
            int uhi = ulo + 4;
            uint32_t af[4][4], bf[4][2];
#pragma unroll
            for (int f = 0; f < 4; ++f) {
                int r0 = warp_m * 64 + f * 16 + (lane >> 2);
                af[f][0] = lds_sw(As32, r0,     ulo);
                af[f][1] = lds_sw(As32, r0 + 8, ulo);
                af[f][2] = lds_sw(As32, r0,     uhi);
                af[f][3] = lds_sw(As32, r0 + 8, uhi);
            }
#pragma unroll
            for (int nf = 0; nf < 4; ++nf) {
                int n0 = warp_n * 32 + nf * 8 + (lane >> 2);
                bf[nf][0] = lds_sw(Bs32, n0, ulo);
                bf[nf][1] = lds_sw(Bs32, n0, uhi);
            }
#pragma unroll
            for (int f = 0; f < 4; ++f)
#pragma unroll
                for (int nf = 0; nf < 4; ++nf) {
                    asm volatile(
                        "mma.sync.aligned.m16n8k16.row.col.f32.f16.f16.f32 "
                        "{%0,%1,%2,%3}, {%4,%5,%6,%7}, {%8,%9}, {%0,%1,%2,%3};\n"
                        : "+f"(acc[f][nf][0]), "+f"(acc[f][nf][1]),
                          "+f"(acc[f][nf][2]), "+f"(acc[f][nf][3])
                        : "r"(af[f][0]), "r"(af[f][1]),
                          "r"(af[f][2]), "r"(af[f][3]),
                          "r"(bf[nf][0]), "r"(bf[nf][1]));
                }
        }
    }

    // epilogue
#pragma unroll
    for (int f = 0; f < 4; ++f) {
        int row = bm + warp_m * 64 + f * 16 + (lane >> 2);
#pragma unroll
        for (int nf = 0; nf < 4; ++nf) {
            int col = bn + warp_n * 32 + nf * 8 + (lane & 3) * 2;
            if constexpr (sizeof(CT) == 2) {
                *(__half2*)((__half*)C + (size_t)row * N + col) =
                    __floats2half2_rn(acc[f][nf][0], acc[f][nf][1]);
                *(__half2*)((__half*)C + (size_t)(row + 8) * N + col) =
                    __floats2half2_rn(acc[f][nf][2], acc[f][nf][3]);
            } else {
                *(float2*)((float*)C + (size_t)row * N + col) =
                    make_float2(acc[f][nf][0], acc[f][nf][1]);
                *(float2*)((float*)C + (size_t)(row + 8) * N + col) =
                    make_float2(acc[f][nf][2], acc[f][nf][3]);
            }
        }
    }
}

// inter = SiLU(gate) * up, written back into gate buffer (half2 vectorized)
__global__ void swiglu_kernel(__half2* __restrict__ gate,
                              const __half2* __restrict__ up, int n2)
{
    int i = blockIdx.x * blockDim.x + threadIdx.x;
    if (i >= n2) return;
    float2 g = __half22float2(gate[i]);
    float2 u = __half22float2(up[i]);
    float r0 = g.x * u.x / (1.f + __expf(-g.x));
    float r1 = g.y * u.y / (1.f + __expf(-g.y));
    gate[i] = __floats2half2_rn(r0, r1);
}

extern "C" void kernel_launch(void* const* d_in, const int* in_sizes, int n_in,
                              void* d_out, int out_size)
{
    const float* x   = (const float*)d_in[0];   // fp16 upcast to fp32 by harness
    const int*   gqw = (const int*)  d_in[1];
    const float* gsc = (const float*)d_in[2];
    const int*   gze = (const int*)  d_in[3];
    const int*   uqw = (const int*)  d_in[4];
    const float* usc = (const float*)d_in[5];
    const int*   uze = (const int*)  d_in[6];
    const int*   dqw = (const int*)  d_in[7];
    const float* dsc = (const float*)d_in[8];
    const int*   dze = (const int*)  d_in[9];
    float* out = (float*)d_out;                 // fp16 output upcast to fp32

    __half *gate_p = nullptr, *up_p = nullptr;
    cudaGetSymbolAddress((void**)&gate_p, g_gate);
    cudaGetSymbolAddress((void**)&up_p,   g_up);

    dim3 blk(256);
    dim3 grid1(ISZ / BN, MROWS / BM);   // 86 x 32
    gemm_gptq<float, __half><<<grid1, blk>>>(x, gqw, gsc, gze, gate_p, ISZ, HID);
    gemm_gptq<float, __half><<<grid1, blk>>>(x, uqw, usc, uze, up_p,   ISZ, HID);

    int n2 = (MROWS * ISZ) / 2;
    swiglu_kernel<<<(n2 + 255) / 256, 256>>>((__half2*)gate_p,
                                             (const __half2*)up_p, n2);

    dim3 grid2(HID / BN, MROWS / BM);   // 32 x 32
    gemm_gptq<__half, float><<<grid2, blk>>>(gate_p, dqw, dsc, dze, out, HID, ISZ);
}

// round 7
// speedup vs baseline: 2.3692x; 2.3692x over previous
#include <cuda_runtime.h>
#include <cuda_fp16.h>
#include <stdint.h>

// Problem dims (fixed by the dataset)
#define HID   4096
#define ISZ   11008
#define MROWS 4096   // 2 * 2048

// Scratch (allocation-free rule: __device__ globals)
__device__ __half g_wg[(size_t)HID * ISZ];    // gate weight, [N=ISZ][K=HID] (W^T, k contig)
__device__ __half g_wu[(size_t)HID * ISZ];    // up weight
__device__ __half g_wd[(size_t)ISZ * HID];    // down weight, [N=HID][K=ISZ]
__device__ __half g_xh[(size_t)MROWS * HID];  // x in fp16
__device__ __half g_gate[(size_t)MROWS * ISZ];
__device__ __half g_up  [(size_t)MROWS * ISZ];

#define BM 128
#define BN 128
#define BK 64

// ---------------------------------------------------------------------------
// Dequant: qw [K/8, N] int32 (8 nibbles along K), scales [G, N] fp32,
// zeros [G, N/8] int32 (8 nibbles along N).  w = q*s - (z+1)*s.
// Output W^T: [N][K] fp16, k contiguous.
// Grid: (K/32, N/256), block 256. Thread: one n, 4 consecutive k-words (32 k).
// ---------------------------------------------------------------------------
__global__ void dequant_kernel(const int* __restrict__ qw,
                               const float* __restrict__ sc,
                               const int* __restrict__ zr,
                               __half* __restrict__ WT, int N, int K)
{
    int n   = blockIdx.y * 256 + threadIdx.x;
    int kw0 = blockIdx.x * 4;
    int g   = (kw0 * 8) >> 7;   // group = k / 128
    float s  = sc[(size_t)g * N + n];
    int   zw = zr[(size_t)g * (N >> 3) + (n >> 3)];
    float zs = -(float)(((zw >> ((n & 7) * 4)) & 15) + 1) * s;
    __half* dst = WT + (size_t)n * K + kw0 * 8;
#pragma unroll
    for (int i = 0; i < 4; ++i) {
        uint32_t q = (uint32_t)qw[(size_t)(kw0 + i) * N + n];
        __align__(16) __half2 h[4];
#pragma unroll
        for (int p = 0; p < 4; ++p) {
            float f0 = fmaf((float)(q & 15u), s, zs); q >>= 4;
            float f1 = fmaf((float)(q & 15u), s, zs); q >>= 4;
            h[p] = __floats2half2_rn(f0, f1);
        }
        *(int4*)(dst + i * 8) = *(const int4*)h;
    }
}

// fp32 -> fp16 elementwise (x), 4 per thread
__global__ void convert_x_kernel(const float4* __restrict__ in,
                                 __half2* __restrict__ out, int n4)
{
    int i = blockIdx.x * blockDim.x + threadIdx.x;
    if (i >= n4) return;
    float4 v = in[i];
    out[2 * i]     = __floats2half2_rn(v.x, v.y);
    out[2 * i + 1] = __floats2half2_rn(v.z, v.w);
}

// ---------------------------------------------------------------------------
// fp16 GEMM: C[M,N] = A[M,K] @ W  where W^T is given as B[N][K] (k contig).
// Tiles BM=BN=128, BK=64; 8 warps (2x4), warp tile 64x32; XOR-swizzled smem;
// ldmatrix.x4 fragment loads; register prefetch of the next tile.
// ---------------------------------------------------------------------------
__device__ __forceinline__ void ldsm_x4(uint32_t& r0, uint32_t& r1,
                                        uint32_t& r2, uint32_t& r3, uint32_t a)
{
    asm volatile("ldmatrix.sync.aligned.m8n8.x4.shared.b16 {%0,%1,%2,%3}, [%4];"
                 : "=r"(r0), "=r"(r1), "=r"(r2), "=r"(r3) : "r"(a));
}

template <typename CT>
__global__ __launch_bounds__(256, 2)
void gemm_fp16(const __half* __restrict__ A, const __half* __restrict__ B,
               CT* __restrict__ C, int N, int K)
{
    __shared__ __align__(16) __half As[BM * BK];
    __shared__ __align__(16) __half Bs[BN * BK];

    const int t    = threadIdx.x;
    const int lane = t & 31;
    const int wid  = t >> 5;
    const int warp_m = wid >> 2;     // 0..1
    const int warp_n = wid & 3;      // 0..3
    const int bm = blockIdx.y * BM;
    const int bn = blockIdx.x * BN;

    // global->smem copy mapping: chunk id = t + i*256 -> row = t>>3 + i*32, chunk = t&7
    const int r0 = t >> 3;
    const int c0 = t & 7;
    const __half* Aptr = A + (size_t)(bm + r0) * K + c0 * 8;
    const __half* Bptr = B + (size_t)(bn + r0) * K + c0 * 8;

    // ldmatrix per-lane address bases (XOR swizzle: chunk c of row r at c^(r&7))
    const uint32_t smemA = (uint32_t)__cvta_generic_to_shared(As);
    const uint32_t smemB = (uint32_t)__cvta_generic_to_shared(Bs);
    const int la_row = warp_m * 64 + (lane & 7) + ((lane >> 3) & 1) * 8;
    const int la_kc  = lane >> 4;           // 0/1
    const int sA7    = la_row & 7;
    const uint32_t baseA = smemA + la_row * 128;
    const int lb_row = warp_n * 32 + (lane & 7) + ((lane >> 4) & 1) * 8;
    const int lb_kc  = (lane >> 3) & 1;
    const int sB7    = lb_row & 7;
    const uint32_t baseB = smemB + lb_row * 128;

    float acc[4][4][4];
#pragma unroll
    for (int f = 0; f < 4; ++f)
#pragma unroll
        for (int n = 0; n < 4; ++n)
#pragma unroll
            for (int i = 0; i < 4; ++i) acc[f][n][i] = 0.f;

    const int ntiles = K / BK;
    int4 aR[4], bR[4];

    // prefetch tile 0
#pragma unroll
    for (int i = 0; i < 4; ++i) {
        aR[i] = *(const int4*)(Aptr + (size_t)i * 32 * K);
        bR[i] = *(const int4*)(Bptr + (size_t)i * 32 * K);
    }

    for (int kt = 0; kt < ntiles; ++kt) {
        __syncthreads();   // previous tile's compute finished reading smem
#pragma unroll
        for (int i = 0; i < 4; ++i) {
            int r = r0 + i * 32;
            ((int4*)As)[r * 8 + (c0 ^ (r & 7))] = aR[i];
            ((int4*)Bs)[r * 8 + (c0 ^ (r & 7))] = bR[i];
        }
        __syncthreads();   // tile ready

        if (kt + 1 < ntiles) {
            int k0n = (kt + 1) * BK;
#pragma unroll
            for (int i = 0; i < 4; ++i) {
                aR[i] = *(const int4*)(Aptr + (size_t)i * 32 * K + k0n);
                bR[i] = *(const int4*)(Bptr + (size_t)i * 32 * K + k0n);
            }
        }

#pragma unroll
        for (int ks = 0; ks < 4; ++ks) {
            uint32_t af[4][4], bf[4][2];
            const uint32_t offA = (uint32_t)(((ks * 2 + la_kc) ^ sA7) << 4);
            const uint32_t offB = (uint32_t)(((ks * 2 + lb_kc) ^ sB7) << 4);
#pragma unroll
            for (int f = 0; f < 4; ++f)
                ldsm_x4(af[f][0], af[f][1], af[f][2], af[f][3],
                        baseA + f * 2048 + offA);
#pragma unroll
            for (int p = 0; p < 2; ++p)
                ldsm_x4(bf[2 * p][0], bf[2 * p][1], bf[2 * p + 1][0], bf[2 * p + 1][1],
                        baseB + p * 2048 + offB);
#pragma unroll
            for (int f = 0; f < 4; ++f)
#pragma unroll
                for (int nf = 0; nf < 4; ++nf) {
                    asm volatile(
                        "mma.sync.aligned.m16n8k16.row.col.f32.f16.f16.f32 "
                        "{%0,%1,%2,%3}, {%4,%5,%6,%7}, {%8,%9}, {%0,%1,%2,%3};\n"
                        : "+f"(acc[f][nf][0]), "+f"(acc[f][nf][1]),
                          "+f"(acc[f][nf][2]), "+f"(acc[f][nf][3])
                        : "r"(af[f][0]), "r"(af[f][1]),
                          "r"(af[f][2]), "r"(af[f][3]),
                          "r"(bf[nf][0]), "r"(bf[nf][1]));
                }
        }
    }

    // epilogue
#pragma unroll
    for (int f = 0; f < 4; ++f) {
        int row = bm + warp_m * 64 + f * 16 + (lane >> 2);
#pragma unroll
        for (int nf = 0; nf < 4; ++nf) {
            int col = bn + warp_n * 32 + nf * 8 + (lane & 3) * 2;
            if constexpr (sizeof(CT) == 2) {
                *(__half2*)((__half*)C + (size_t)row * N + col) =
                    __floats2half2_rn(acc[f][nf][0], acc[f][nf][1]);
                *(__half2*)((__half*)C + (size_t)(row + 8) * N + col) =
                    __floats2half2_rn(acc[f][nf][2], acc[f][nf][3]);
            } else {
                *(float2*)((float*)C + (size_t)row * N + col) =
                    make_float2(acc[f][nf][0], acc[f][nf][1]);
                *(float2*)((float*)C + (size_t)(row + 8) * N + col) =
                    make_float2(acc[f][nf][2], acc[f][nf][3]);
            }
        }
    }
}

// inter = SiLU(gate) * up, written back into gate buffer (half2 vectorized)
__global__ void swiglu_kernel(__half2* __restrict__ gate,
                              const __half2* __restrict__ up, int n2)
{
    int i = blockIdx.x * blockDim.x + threadIdx.x;
    if (i >= n2) return;
    float2 g = __half22float2(gate[i]);
    float2 u = __half22float2(up[i]);
    float r0 = g.x * u.x / (1.f + __expf(-g.x));
    float r1 = g.y * u.y / (1.f + __expf(-g.y));
    gate[i] = __floats2half2_rn(r0, r1);
}

extern "C" void kernel_launch(void* const* d_in, const int* in_sizes, int n_in,
                              void* d_out, int out_size)
{
    const float* x   = (const float*)d_in[0];   // fp16 upcast to fp32 by harness
    const int*   gqw = (const int*)  d_in[1];
    const float* gsc = (const float*)d_in[2];
    const int*   gze = (const int*)  d_in[3];
    const int*   uqw = (const int*)  d_in[4];
    const float* usc = (const float*)d_in[5];
    const int*   uze = (const int*)  d_in[6];
    const int*   dqw = (const int*)  d_in[7];
    const float* dsc = (const float*)d_in[8];
    const int*   dze = (const int*)  d_in[9];
    float* out = (float*)d_out;                 // fp16 output upcast to fp32

    __half *wg_p, *wu_p, *wd_p, *xh_p, *gate_p, *up_p;
    cudaGetSymbolAddress((void**)&wg_p,   g_wg);
    cudaGetSymbolAddress((void**)&wu_p,   g_wu);
    cudaGetSymbolAddress((void**)&wd_p,   g_wd);
    cudaGetSymbolAddress((void**)&xh_p,   g_xh);
    cudaGetSymbolAddress((void**)&gate_p, g_gate);
    cudaGetSymbolAddress((void**)&up_p,   g_up);

    // 1) one-time prep: x -> fp16, weights -> fp16 (W^T, [N][K])
    {
        int n4 = (MROWS * HID) / 4;
        convert_x_kernel<<<(n4 + 255) / 256, 256>>>((const float4*)x,
                                                    (__half2*)xh_p, n4);
    }
    dequant_kernel<<<dim3(HID / 32, ISZ / 256), 256>>>(gqw, gsc, gze, wg_p, ISZ, HID);
    dequant_kernel<<<dim3(HID / 32, ISZ / 256), 256>>>(uqw, usc, uze, wu_p, ISZ, HID);
    dequant_kernel<<<dim3(ISZ / 32, HID / 256), 256>>>(dqw, dsc, dze, wd_p, HID, ISZ);

    // 2) GEMMs
    dim3 blk(256);
    dim3 grid1(ISZ / BN, MROWS / BM);   // 86 x 32
    gemm_fp16<__half><<<grid1, blk>>>(xh_p, wg_p, gate_p, ISZ, HID);
    gemm_fp16<__half><<<grid1, blk>>>(xh_p, wu_p, up_p,   ISZ, HID);

    int n2 = (MROWS * ISZ) / 2;
    swiglu_kernel<<<(n2 + 255) / 256, 256>>>((__half2*)gate_p,
                                             (const __half2*)up_p, n2);

    dim3 grid2(HID / BN, MROWS / BM);   // 32 x 32
    gemm_fp16<float><<<grid2, blk>>>(gate_p, wd_p, out, HID, ISZ);
}